// round 8
// baseline (speedup 1.0000x reference)
#include <cuda_runtime.h>
#include <cuda_bf16.h>
#include <stdint.h>

#define BB 32
#define KK 512
#define CC 32
#define NSL 16            // slices per batch (32 rows each)
#define SROWS 32          // rows per slice
#define NPH 4             // phases (8 batches per phase)
#define NBLK 128
#define NW 16             // warps per block

// Scratch (no allocations allowed)
__device__ float  g_U[BB * KK * CC];                   // U[b][k][o]  (2 MB)
__device__ float4 g_Vp4[BB * NSL * CC * (KK / 4)];     // Vp[b][sl][o][j/4] (33.5 MB)
__device__ float  g_s[BB * CC];
__device__ unsigned g_cnt[BB];
__device__ unsigned g_flag[BB];
__device__ unsigned g_done;

union F2U { float2 f; unsigned long long u; };
union F4U { float4 f; unsigned long long u[2]; };

__device__ __forceinline__ unsigned long long ffma2(unsigned long long a,
                                                    unsigned long long b,
                                                    unsigned long long c) {
    unsigned long long d;
    asm("fma.rn.f32x2 %0, %1, %2, %3;" : "=l"(d) : "l"(a), "l"(b), "l"(c));
    return d;
}
__device__ __forceinline__ unsigned long long pack2(float v) {
    unsigned long long r;
    asm("mov.b64 %0, {%1, %1};" : "=l"(r) : "f"(v));
    return r;
}
__device__ __forceinline__ void cp16(uint32_t smem_addr, const void* gptr) {
    asm volatile("cp.async.cg.shared.global [%0], [%1], 16;"
                 :: "r"(smem_addr), "l"(gptr));
}
__device__ __forceinline__ unsigned ld_acq(const unsigned* p) {
    unsigned v;
    asm volatile("ld.acquire.gpu.global.u32 %0, [%1];" : "=r"(v) : "l"(p) : "memory");
    return v;
}
__device__ __forceinline__ void red_rel_add(unsigned* p, unsigned v) {
    asm volatile("red.release.gpu.global.add.u32 [%0], %1;" :: "l"(p), "r"(v) : "memory");
}

// global sub-chunk (16-row) base in float4 units: u in [0,8)
__device__ __forceinline__ size_t rowbase_f4(int u, int g) {
    int p = u >> 1;
    int S = p * NBLK + g;
    int b = S >> 4;                    // 16 slices per batch
    int r = (S & 15) * SROWS + (u & 1) * 16;
    return ((size_t)(b * KK + r)) * (KK / 4);
}

__global__ __launch_bounds__(512) void fused(const float* __restrict__ x,
                                             const float* __restrict__ wc,
                                             const float* __restrict__ bc,
                                             const float* __restrict__ wr,
                                             const float* __restrict__ br,
                                             float4* __restrict__ out) {
    __shared__ float4 xs4[2][16 * (KK / 4)];     // 64 KB
    __shared__ float  u_part[16 * NW * CC];      // 32 KB
    __shared__ float  wr_s[SROWS * CC];          // 4 KB
    __shared__ float  red_s[NW];
    __shared__ int    sh_ready;

    const int g = blockIdx.x;
    const int t = threadIdx.x;
    const int o = t & 31;
    const int w = t >> 5;
    const int o_g = g & 31;       // store assignment: o-plane
    const int q_g = g >> 5;       // store assignment: quarter

    const float4* x4 = (const float4*)x;
    const uint32_t xs_sa[2] = {
        (uint32_t)__cvta_generic_to_shared(&xs4[0][0]),
        (uint32_t)__cvta_generic_to_shared(&xs4[1][0])
    };

    // prefetch sub-chunk 0
    {
        const float4* src = x4 + rowbase_f4(0, g);
#pragma unroll
        for (int i = 0; i < 4; i++)
            cp16(xs_sa[0] + (uint32_t)(t + i * 512) * 16u, src + t + i * 512);
        asm volatile("cp.async.commit_group;");
    }

    // persistent w_col slice: 8 float4 = 16 packed f32x2
    unsigned long long wcr[16];
#pragma unroll
    for (int qq = 0; qq < 8; qq++) {
        F4U v; v.f = ((const float4*)wc)[o * (KK / 4) + w + 16 * qq];
        wcr[2 * qq] = v.u[0]; wcr[2 * qq + 1] = v.u[1];
    }

    unsigned long long Vacc[16];
    int nb = 0;   // next batch to store

    for (int p = 0; p < NPH; p++) {
        const int S = p * NBLK + g;
        const int b = S >> 4;
        const int sl = S & 15;
        const int r0 = sl * SROWS;

#pragma unroll
        for (int qq = 0; qq < 16; qq++) Vacc[qq] = 0ull;

        for (int h = 0; h < 2; h++) {
            const int u = p * 2 + h;
            asm volatile("cp.async.wait_group 0;" ::: "memory");
            __syncthreads();   // xs[u&1] ready; previous u_part reads done

            if (u + 1 < 2 * NPH) {
                const float4* src = x4 + rowbase_f4(u + 1, g);
                const uint32_t dst = xs_sa[(u + 1) & 1];
#pragma unroll
                for (int i = 0; i < 4; i++)
                    cp16(dst + (uint32_t)(t + i * 512) * 16u, src + t + i * 512);
                asm volatile("cp.async.commit_group;");
            }

            if (h == 0) {
                // stage w_row slice for this 32-row slice: wr_s[r][o]
#pragma unroll
                for (int i = 0; i < 2; i++) {
                    int idx = t + i * 512;
                    int rr = idx >> 5, oo = idx & 31;
                    wr_s[idx] = wr[oo * KK + r0 + rr];
                }
                __syncthreads();
            }

            const float4* xsb = xs4[u & 1];
#pragma unroll
            for (int r = 0; r < 16; r++) {
                const unsigned long long wr2 = pack2(wr_s[(h * 16 + r) * 32 + o]);
                const float4* xr4 = xsb + r * (KK / 4);
                unsigned long long ua = 0ull, ub = 0ull;
#pragma unroll
                for (int qq = 0; qq < 8; qq++) {
                    F4U xv; xv.f = xr4[w + 16 * qq];     // 32-lane broadcast
                    Vacc[2 * qq]     = ffma2(wr2, xv.u[0], Vacc[2 * qq]);
                    Vacc[2 * qq + 1] = ffma2(wr2, xv.u[1], Vacc[2 * qq + 1]);
                    ua = ffma2(wcr[2 * qq],     xv.u[0], ua);
                    ub = ffma2(wcr[2 * qq + 1], xv.u[1], ub);
                }
                F2U us; us.u = ua; F2U ut; ut.u = ub;
                u_part[(r * NW + w) * 32 + o] = (us.f.x + us.f.y) + (ut.f.x + ut.f.y);
            }
            __syncthreads();

            // cross-warp U reduce + coalesced writeback (16 rows x 32 o)
            {
                const int rr = t >> 5, oo = t & 31;
                float s = 0.f;
#pragma unroll
                for (int wi = 0; wi < NW; wi++) s += u_part[(rr * NW + wi) * 32 + oo];
                g_U[((size_t)(b * KK + r0 + h * 16 + rr)) * CC + oo] = s;
            }
        }

        // V-partial writeback for this slice
        {
            float4* Vg = g_Vp4 + ((size_t)((b * NSL + sl) * CC + o)) * (KK / 4);
#pragma unroll
            for (int qq = 0; qq < 8; qq++) {
                F4U v; v.u[0] = Vacc[2 * qq]; v.u[1] = Vacc[2 * qq + 1];
                Vg[w + 16 * qq] = v.f;
            }
        }

        // signal slice completion (release)
        __threadfence();
        __syncthreads();
        if (t == 0) red_rel_add(&g_cnt[b], 1);

        // ---- reduction duty: blocks [32p, 32p+32) reduce batches 8p..8p+7 ----
        if ((g >> 5) == p) {
            const int local = g & 31;
            const int db = 8 * p + (local >> 2);
            const int ob = (local & 3) * 8;
            if (t == 0) { while (ld_acq(&g_cnt[db]) < NSL) { } }
            __syncthreads();

            const int o_l = t >> 6;          // 0..7
            const int tj = t & 63;
            const int oo = ob + o_l;
            const float bcv = bc[oo], brv = br[oo];
            const float* Vpf = (const float*)g_Vp4;
            float acc = 0.f;
#pragma unroll
            for (int jj = 0; jj < 8; jj++) {
                const int j = tj + 64 * jj;
                float V = 0.f;
#pragma unroll
                for (int s2 = 0; s2 < NSL; s2++)
                    V += Vpf[((size_t)((db * NSL + s2) * CC + oo)) * KK + j];
                float U = g_U[((size_t)(db * KK + j)) * CC + oo];
                acc += (V + brv) * (U + bcv);
            }
#pragma unroll
            for (int m = 16; m > 0; m >>= 1) acc += __shfl_xor_sync(0xffffffffu, acc, m);
            if ((t & 31) == 0) red_s[t >> 5] = acc;
            __syncthreads();
            if (t < 8) g_s[db * CC + ob + t] = red_s[2 * t] + red_s[2 * t + 1];
            __threadfence();
            __syncthreads();
            if (t == 0) red_rel_add(&g_flag[db], 1);
        }

        // ---- non-blocking store drain ----
        for (;;) {
            if (nb >= BB) break;
            if (t == 0) sh_ready = (ld_acq(&g_flag[nb]) >= 4) ? 1 : 0;
            __syncthreads();
            const int go = sh_ready;
            __syncthreads();
            if (!go) break;
            const float sv = g_s[nb * CC + o_g];
            const float4 val = make_float4(sv, sv, sv, sv);
            float4* p4 = out + (size_t)(nb * CC + o_g) * 65536 + (size_t)q_g * 16384 + t;
#pragma unroll
            for (int i = 0; i < 32; i++) p4[i * 512] = val;
            nb++;
        }
    }

    // ---- blocking final drain ----
    while (nb < BB) {
        if (t == 0) { while (ld_acq(&g_flag[nb]) < 4) { } }
        __syncthreads();
        const float sv = g_s[nb * CC + o_g];
        const float4 val = make_float4(sv, sv, sv, sv);
        float4* p4 = out + (size_t)(nb * CC + o_g) * 65536 + (size_t)q_g * 16384 + t;
#pragma unroll
        for (int i = 0; i < 32; i++) p4[i * 512] = val;
        nb++;
    }

    // ---- counter reset behind a 128-way done barrier (deterministic replays) ----
    __threadfence();
    __syncthreads();
    if (t == 0) red_rel_add(&g_done, 1);
    if (g == 0 && t == 0) {
        while (ld_acq(&g_done) < NBLK) { }
        for (int i = 0; i < BB; i++) { g_cnt[i] = 0; g_flag[i] = 0; }
        g_done = 0;
        __threadfence();
    }
}

extern "C" void kernel_launch(void* const* d_in, const int* in_sizes, int n_in,
                              void* d_out, int out_size) {
    const float* x  = (const float*)d_in[0];
    const float* wc = (const float*)d_in[1];
    const float* bc = (const float*)d_in[2];
    const float* wr = (const float*)d_in[3];
    const float* br = (const float*)d_in[4];

    fused<<<NBLK, 512>>>(x, wc, bc, wr, br, (float4*)d_out);
}

// round 9
// speedup vs baseline: 1.0669x; 1.0669x over previous
#include <cuda_runtime.h>
#include <cuda_bf16.h>
#include <stdint.h>

#define BB 32
#define KK 512
#define CC 32
#define NC 64               // compute blocks
#define NBLK 148            // total blocks (one per SM)
#define NSB (NBLK - NC)     // 84 store blocks
#define PPB 16              // compute blocks per batch
#define RPB 32              // rows per (block,batch)
#define NPH 8               // phases (4 batches per phase)
#define NSTEP 16            // 16-row subchunks per block (NPH*2)
#define PLANES (BB * CC)    // 1024 output planes of 1MB

// Scratch (no allocations allowed)
__device__ float  g_U[BB * KK * CC];                    // 2 MB
__device__ float4 g_Vp4[BB * PPB * CC * (KK / 4)];      // 32 MB
__device__ float  g_s[BB * CC];
__device__ unsigned g_cnt[BB];
__device__ unsigned g_sflag[BB];
__device__ unsigned g_done;

union F2U { float2 f; unsigned long long u; };
union F4U { float4 f; unsigned long long u[2]; };

__device__ __forceinline__ unsigned long long ffma2(unsigned long long a,
                                                    unsigned long long b,
                                                    unsigned long long c) {
    unsigned long long d;
    asm("fma.rn.f32x2 %0, %1, %2, %3;" : "=l"(d) : "l"(a), "l"(b), "l"(c));
    return d;
}
__device__ __forceinline__ unsigned long long pack2(float v) {
    unsigned long long r;
    asm("mov.b64 %0, {%1, %1};" : "=l"(r) : "f"(v));
    return r;
}
__device__ __forceinline__ void cp16(uint32_t smem_addr, const void* gptr) {
    asm volatile("cp.async.cg.shared.global [%0], [%1], 16;"
                 :: "r"(smem_addr), "l"(gptr));
}
__device__ __forceinline__ unsigned ld_acq(const unsigned* p) {
    unsigned v;
    asm volatile("ld.acquire.gpu.global.u32 %0, [%1];" : "=r"(v) : "l"(p) : "memory");
    return v;
}
__device__ __forceinline__ void red_rel_add(unsigned* p, unsigned v) {
    asm volatile("red.release.gpu.global.add.u32 [%0], %1;" :: "l"(p), "r"(v) : "memory");
}

// float4 base of 16-row subchunk n for compute block (m, r0)
__device__ __forceinline__ size_t stepbase_f4(int n, int m, int r0) {
    int b = 4 * (n >> 1) + m;
    return ((size_t)(b * KK + r0 + (n & 1) * 16)) * (KK / 4);
}

__global__ __launch_bounds__(512) void fused2(const float* __restrict__ x,
                                              const float* __restrict__ wc,
                                              const float* __restrict__ bc,
                                              const float* __restrict__ wr,
                                              const float* __restrict__ br,
                                              float4* __restrict__ out) {
    __shared__ float4 xs4[2][16 * (KK / 4)];     // 64 KB
    __shared__ float  u_part[16 * 16 * CC];      // 32 KB
    __shared__ float  wr_s[RPB * CC];            // 4 KB

    const int g = blockIdx.x;
    const int t = threadIdx.x;

    if (g < NC) {
        // ================= COMPUTE BLOCK =================
        const int m   = g >> 4;          // batch sub-group (0..3)
        const int idx = g & 15;          // row-chunk within batch
        const int r0  = idx * RPB;
        const int o   = t & 31;
        const int w   = t >> 5;

        const float4* x4 = (const float4*)x;
        const uint32_t xs_sa[2] = {
            (uint32_t)__cvta_generic_to_shared(&xs4[0][0]),
            (uint32_t)__cvta_generic_to_shared(&xs4[1][0])
        };

        // prefetch subchunk 0
        {
            const float4* src = x4 + stepbase_f4(0, m, r0);
#pragma unroll
            for (int i = 0; i < 4; i++)
                cp16(xs_sa[0] + (uint32_t)(t + i * 512) * 16u, src + t + i * 512);
            asm volatile("cp.async.commit_group;");
        }

        // w_row slice (rows r0..r0+31) — batch-independent, load once
#pragma unroll
        for (int i = 0; i < (RPB * CC) / 512; i++) {
            int id = t + i * 512;
            int rr = id >> 5, oo = id & 31;
            wr_s[id] = wr[oo * KK + r0 + rr];
        }

        // persistent w_col slice: 8 float4 = 16 packed f32x2
        unsigned long long wcr[16];
#pragma unroll
        for (int qq = 0; qq < 8; qq++) {
            F4U v; v.f = ((const float4*)wc)[o * (KK / 4) + w + 16 * qq];
            wcr[2 * qq] = v.u[0]; wcr[2 * qq + 1] = v.u[1];
        }

        unsigned long long Vacc[16];

        for (int n = 0; n < NSTEP; n++) {
            const int ph = n >> 1, h = n & 1;
            const int b = 4 * ph + m;

            if (h == 0) {
#pragma unroll
                for (int qq = 0; qq < 16; qq++) Vacc[qq] = 0ull;
            }

            asm volatile("cp.async.wait_group 0;" ::: "memory");
            __syncthreads();

            if (n + 1 < NSTEP) {
                const float4* src = x4 + stepbase_f4(n + 1, m, r0);
                const uint32_t dst = xs_sa[(n + 1) & 1];
#pragma unroll
                for (int i = 0; i < 4; i++)
                    cp16(dst + (uint32_t)(t + i * 512) * 16u, src + t + i * 512);
                asm volatile("cp.async.commit_group;");
            }

            const float4* xsb = xs4[n & 1];
#pragma unroll
            for (int r = 0; r < 16; r++) {
                const unsigned long long wr2 = pack2(wr_s[(h * 16 + r) * 32 + o]);
                const float4* xr4 = xsb + r * (KK / 4);
                unsigned long long ua = 0ull, ub = 0ull;
#pragma unroll
                for (int qq = 0; qq < 8; qq++) {
                    F4U xv; xv.f = xr4[w + 16 * qq];     // 32-lane broadcast
                    Vacc[2 * qq]     = ffma2(wr2, xv.u[0], Vacc[2 * qq]);
                    Vacc[2 * qq + 1] = ffma2(wr2, xv.u[1], Vacc[2 * qq + 1]);
                    ua = ffma2(wcr[2 * qq],     xv.u[0], ua);
                    ub = ffma2(wcr[2 * qq + 1], xv.u[1], ub);
                }
                F2U us; us.u = ua; F2U ut; ut.u = ub;
                u_part[(r * 16 + w) * 32 + o] = (us.f.x + us.f.y) + (ut.f.x + ut.f.y);
            }
            __syncthreads();

            // cross-warp U reduce + coalesced writeback
            {
                const int rr = t >> 5, oo = t & 31;
                float s = 0.f;
#pragma unroll
                for (int wi = 0; wi < 16; wi++) s += u_part[(rr * 16 + wi) * 32 + oo];
                g_U[((size_t)(b * KK + r0 + h * 16 + rr)) * CC + oo] = s;
            }

            if (h == 1) {
                // V-partial writeback for this (batch, chunk)
                float4* Vg = g_Vp4 + ((size_t)((b * PPB + idx) * CC + o)) * (KK / 4);
#pragma unroll
                for (int qq = 0; qq < 8; qq++) {
                    F4U v; v.u[0] = Vacc[2 * qq]; v.u[1] = Vacc[2 * qq + 1];
                    Vg[w + 16 * qq] = v.f;
                }
                __threadfence();
                __syncthreads();
                if (t == 0) red_rel_add(&g_cnt[b], 1);
            }
        }
    } else {
        // ================= STORE BLOCK =================
        const int j = g - NC;
        for (int P = j; P < PLANES; P += NSB) {
            const int b = P >> 5;
            const int o = P & 31;

            if ((P & 31) == 0) {
                // reducer duty: compute s[b, :] once batch b's partials land
                if (t == 0) { while (ld_acq(&g_cnt[b]) < PPB) __nanosleep(128); }
                __syncthreads();

                const int oo = t >> 4;       // 0..31
                const int jl = t & 15;
                const float bcv = bc[oo], brv = br[oo];
                const float* Vpf = (const float*)g_Vp4;
                float acc = 0.f;
#pragma unroll 4
                for (int i = 0; i < 32; i++) {
                    const int k = jl + 16 * i;
                    float V = brv;
#pragma unroll
                    for (int s2 = 0; s2 < PPB; s2++)
                        V += Vpf[((size_t)((b * PPB + s2) * CC + oo)) * KK + k];
                    float U = g_U[((size_t)(b * KK + k)) * CC + oo] + bcv;
                    acc += V * U;
                }
                acc += __shfl_xor_sync(0xffffffffu, acc, 8);
                acc += __shfl_xor_sync(0xffffffffu, acc, 4);
                acc += __shfl_xor_sync(0xffffffffu, acc, 2);
                acc += __shfl_xor_sync(0xffffffffu, acc, 1);
                if (jl == 0) g_s[b * CC + oo] = acc;
                __threadfence();
                __syncthreads();
                if (t == 0) red_rel_add(&g_sflag[b], 1);
            } else {
                if (t == 0) { while (ld_acq(&g_sflag[b]) < 1) __nanosleep(128); }
                __syncthreads();
            }

            const float sv = g_s[b * CC + o];
            const float4 val = make_float4(sv, sv, sv, sv);
            float4* p4 = out + (size_t)P * 65536 + t;
#pragma unroll
            for (int i = 0; i < 128; i++) p4[i * 512] = val;
        }
    }

    // ---- done barrier + counter reset (deterministic graph replays) ----
    __threadfence();
    __syncthreads();
    if (t == 0) red_rel_add(&g_done, 1);
    if (g == NBLK - 1 && t == 0) {
        while (ld_acq(&g_done) < NBLK) __nanosleep(128);
        for (int i = 0; i < BB; i++) { g_cnt[i] = 0; g_sflag[i] = 0; }
        g_done = 0;
        __threadfence();
    }
}

extern "C" void kernel_launch(void* const* d_in, const int* in_sizes, int n_in,
                              void* d_out, int out_size) {
    const float* x  = (const float*)d_in[0];
    const float* wc = (const float*)d_in[1];
    const float* bc = (const float*)d_in[2];
    const float* wr = (const float*)d_in[3];
    const float* br = (const float*)d_in[4];

    fused2<<<NBLK, 512>>>(x, wc, bc, wr, br, (float4*)d_out);
}

// round 12
// speedup vs baseline: 1.3558x; 1.2708x over previous
#include <cuda_runtime.h>
#include <cuda_bf16.h>
#include <stdint.h>

#define BB 32
#define KK 512
#define CC 32
#define NBLK 148          // one block per SM, all co-resident
#define NCB 128           // blocks with compute duty
#define NSTEP 16          // 4 units x 4 chunks per compute block
#define PLANES 1024       // 1MB output planes

// Scratch (no allocations allowed)
__device__ float    g_U2[BB * KK * 64];       // [b][k][half*32+o]  4 MB
__device__ float    g_Vp[BB * 8 * CC * KK];   // [(b*8+tile)*32+o][j] 16 MB
__device__ float    g_s[BB * CC];
__device__ unsigned g_cnt[BB];
__device__ unsigned g_sflag[BB];
__device__ unsigned g_done;

union F2U { float2 f; unsigned long long u; };
union F4U { float4 f; unsigned long long u[2]; };

__device__ __forceinline__ unsigned long long ffma2(unsigned long long a,
                                                    unsigned long long b,
                                                    unsigned long long c) {
    unsigned long long d;
    asm("fma.rn.f32x2 %0, %1, %2, %3;" : "=l"(d) : "l"(a), "l"(b), "l"(c));
    return d;
}
__device__ __forceinline__ unsigned long long pack2(float v) {
    unsigned long long r;
    asm("mov.b64 %0, {%1, %1};" : "=l"(r) : "f"(v));
    return r;
}
__device__ __forceinline__ void cp16(uint32_t smem_addr, const void* gptr) {
    asm volatile("cp.async.cg.shared.global [%0], [%1], 16;"
                 :: "r"(smem_addr), "l"(gptr));
}
__device__ __forceinline__ unsigned ld_acq(const unsigned* p) {
    unsigned v;
    asm volatile("ld.acquire.gpu.global.u32 %0, [%1];" : "=r"(v) : "l"(p) : "memory");
    return v;
}
__device__ __forceinline__ void red_rel_add(unsigned* p, unsigned v) {
    asm volatile("red.release.gpu.global.add.u32 [%0], %1;" :: "l"(p), "r"(v) : "memory");
}
#define BAR_C() asm volatile("bar.sync 1, 256;" ::: "memory")
#define BAR_S() asm volatile("bar.sync 2, 256;" ::: "memory")

// unit u = g + 128*i :  b = u>>4, tile = (u&15)>>1, half = u&1
__device__ __forceinline__ size_t chunkbase_f4(int g, int n) {
    int u = g + 128 * (n >> 2);
    int b = u >> 4, sub = u & 15;
    int tile = sub >> 1, half = sub & 1;
    return ((size_t)(b * KK + tile * 64 + (n & 3) * 16)) * 128 + half * 64;
}

__global__ __launch_bounds__(512) void fused3(const float* __restrict__ x,
                                              const float* __restrict__ wc,
                                              const float* __restrict__ bc,
                                              const float* __restrict__ wr,
                                              const float* __restrict__ br,
                                              float4* __restrict__ out) {
    __shared__ float4 xs4[2][1024];          // 32 KB (16 rows x 64 f4, double)
    __shared__ float  u_part[16 * 8 * 32];   // 16 KB
    __shared__ float  wr_s[64 * 32];         // 8 KB

    const int g = blockIdx.x;
    const int t = threadIdx.x;

    if (t < 256) {
        // ======================= COMPUTE GROUP (warps 0-7) =======================
        if (g < NCB) {
            const int o = t & 31;
            const int w = t >> 5;            // 0..7
            const float4* x4 = (const float4*)x;
            const uint32_t sa[2] = {
                (uint32_t)__cvta_generic_to_shared(&xs4[0][0]),
                (uint32_t)__cvta_generic_to_shared(&xs4[1][0])
            };
            const int ldrow = t >> 6;        // 0..3
            const int ldf   = t & 63;

            // prefetch chunk 0
            {
                const float4* src = x4 + chunkbase_f4(g, 0);
#pragma unroll
                for (int i = 0; i < 4; i++)
                    cp16(sa[0] + (uint32_t)((ldrow + 4 * i) * 64 + ldf) * 16u,
                         src + (ldrow + 4 * i) * 128 + ldf);
                asm volatile("cp.async.commit_group;");
            }

            unsigned long long wcr[16];
            unsigned long long Vacc[16];

            for (int n = 0; n < NSTEP; n++) {
                const int u    = g + 128 * (n >> 2);
                const int b    = u >> 4;
                const int sub  = u & 15;
                const int tile = sub >> 1;
                const int half = sub & 1;
                const int i0   = tile * 64;
                const int c    = n & 3;

                asm volatile("cp.async.wait_group 0;" ::: "memory");
                BAR_C();   // xs[n&1] ready; previous buffer reads + wr_s reads done

                if (n + 1 < NSTEP) {
                    const float4* src = x4 + chunkbase_f4(g, n + 1);
                    const uint32_t dst = sa[(n + 1) & 1];
#pragma unroll
                    for (int i = 0; i < 4; i++)
                        cp16(dst + (uint32_t)((ldrow + 4 * i) * 64 + ldf) * 16u,
                             src + (ldrow + 4 * i) * 128 + ldf);
                    asm volatile("cp.async.commit_group;");
                }

                if (c == 0) {
                    // stage w_row rows i0..i0+63 and reload w_col slice for this half
#pragma unroll
                    for (int i = 0; i < 8; i++) {
                        int idx = t + 256 * i;
                        int rr = idx >> 5, oo = idx & 31;
                        wr_s[idx] = wr[oo * KK + i0 + rr];
                    }
#pragma unroll
                    for (int q = 0; q < 8; q++) {
                        F4U v; v.f = ((const float4*)wc)[o * 128 + half * 64 + w + 8 * q];
                        wcr[2 * q] = v.u[0]; wcr[2 * q + 1] = v.u[1];
                    }
#pragma unroll
                    for (int q = 0; q < 16; q++) Vacc[q] = 0ull;
                    BAR_C();   // wr_s ready
                }

                const float4* xsb = xs4[n & 1];
#pragma unroll
                for (int r = 0; r < 16; r++) {
                    const unsigned long long wr2 = pack2(wr_s[(c * 16 + r) * 32 + o]);
                    const float4* xr4 = xsb + r * 64;
                    unsigned long long ua = 0ull, ub = 0ull;
#pragma unroll
                    for (int q = 0; q < 8; q++) {
                        F4U xv; xv.f = xr4[w + 8 * q];      // 32-lane broadcast
                        Vacc[2 * q]     = ffma2(wr2, xv.u[0], Vacc[2 * q]);
                        Vacc[2 * q + 1] = ffma2(wr2, xv.u[1], Vacc[2 * q + 1]);
                        ua = ffma2(wcr[2 * q],     xv.u[0], ua);
                        ub = ffma2(wcr[2 * q + 1], xv.u[1], ub);
                    }
                    F2U us; us.u = ua; F2U ut; ut.u = ub;
                    u_part[(r * 8 + w) * 32 + o] = (us.f.x + us.f.y) + (ut.f.x + ut.f.y);
                }
                BAR_C();   // u_part complete

                // cross-warp U reduce + writeback (half-partial)
#pragma unroll
                for (int e = t; e < 512; e += 256) {
                    int rr = e >> 5, oo = e & 31;
                    float s = 0.f;
#pragma unroll
                    for (int wi = 0; wi < 8; wi++) s += u_part[(rr * 8 + wi) * 32 + oo];
                    g_U2[((size_t)(b * KK + i0 + c * 16 + rr)) * 64 + half * 32 + oo] = s;
                }

                if (c == 3) {
                    // V-partial writeback for this unit (j-half of [o][512])
                    float4* Vg4 = (float4*)(g_Vp + ((size_t)((b * 8 + tile) * 32 + o)) * KK)
                                  + half * 64;
#pragma unroll
                    for (int q = 0; q < 8; q++) {
                        F4U v; v.u[0] = Vacc[2 * q]; v.u[1] = Vacc[2 * q + 1];
                        Vg4[w + 8 * q] = v.f;
                    }
                    __threadfence();
                    BAR_C();
                    if (t == 0) red_rel_add(&g_cnt[b], 1);

                    // reduction duty: block 4*db reduces batch db right when ready
                    if ((g & 3) == 0 && (n >> 2) == (g >> 5)) {
                        const int db = g >> 2;
                        if (t == 0) { while (ld_acq(&g_cnt[db]) < 16) __nanosleep(64); }
                        BAR_C();

                        const int oo = t >> 3, jl = t & 7;
                        const float bcv = bc[oo], brv = br[oo];
                        float acc = 0.f;
#pragma unroll 8
                        for (int jj = 0; jj < 64; jj++) {
                            const int j = jl + 8 * jj;
                            float V = brv;
#pragma unroll
                            for (int t2 = 0; t2 < 8; t2++)
                                V += __ldcg(&g_Vp[((size_t)((db * 8 + t2) * 32 + oo)) * KK + j]);
                            float U = __ldcg(&g_U2[((size_t)(db * KK + j)) * 64 + oo])
                                    + __ldcg(&g_U2[((size_t)(db * KK + j)) * 64 + 32 + oo])
                                    + bcv;
                            acc += V * U;
                        }
                        acc += __shfl_xor_sync(0xffffffffu, acc, 1);
                        acc += __shfl_xor_sync(0xffffffffu, acc, 2);
                        acc += __shfl_xor_sync(0xffffffffu, acc, 4);
                        if (jl == 0) g_s[db * CC + oo] = acc;
                        __threadfence();
                        BAR_C();
                        if (t == 0) red_rel_add(&g_sflag[db], 1);
                    }
                }
            }
        }
        // blocks >= NCB: compute group idle
    } else {
        // ======================= STORE GROUP (warps 8-15) =======================
        const int ts = t - 256;
        for (int P = g; P < PLANES; P += NBLK) {
            const int b = P >> 5;
            const int o = P & 31;
            if (ts == 0) { while (ld_acq(&g_sflag[b]) < 1) __nanosleep(128); }
            BAR_S();
            const float sv = __ldcg(&g_s[b * CC + o]);
            const float4 val = make_float4(sv, sv, sv, sv);
            float4* p4 = out + (size_t)P * 65536 + ts;
#pragma unroll 64
            for (int i = 0; i < 256; i++) p4[i * 256] = val;
        }
    }

    // ---- done barrier + counter reset (deterministic graph replays) ----
    __threadfence();
    __syncthreads();
    if (t == 0) red_rel_add(&g_done, 1);
    if (g == NBLK - 1 && t == 0) {
        while (ld_acq(&g_done) < NBLK) __nanosleep(128);
        for (int i = 0; i < BB; i++) { g_cnt[i] = 0; g_sflag[i] = 0; }
        g_done = 0;
        __threadfence();
    }
}

extern "C" void kernel_launch(void* const* d_in, const int* in_sizes, int n_in,
                              void* d_out, int out_size) {
    const float* x  = (const float*)d_in[0];
    const float* wc = (const float*)d_in[1];
    const float* bc = (const float*)d_in[2];
    const float* wr = (const float*)d_in[3];
    const float* br = (const float*)d_in[4];

    fused3<<<NBLK, 512>>>(x, wc, bc, wr, br, (float4*)d_out);
}

// round 15
// speedup vs baseline: 1.5114x; 1.1148x over previous
#include <cuda_runtime.h>
#include <cuda_bf16.h>
#include <stdint.h>

#define BB 32
#define KK 512
#define CC 32
#define NCHK 64          // chunks of 8 rows
#define CROWS 8

union F2U { float2 f; unsigned long long u; };
union F4U { float4 f; unsigned long long u[2]; };

__device__ __forceinline__ unsigned long long ffma2(unsigned long long a,
                                                    unsigned long long b,
                                                    unsigned long long c) {
    unsigned long long d;
    asm("fma.rn.f32x2 %0, %1, %2, %3;" : "=l"(d) : "l"(a), "l"(b), "l"(c));
    return d;
}
__device__ __forceinline__ unsigned long long pack2(float v) {
    unsigned long long r;
    asm("mov.b64 %0, {%1, %1};" : "=l"(r) : "f"(v));
    return r;
}
__device__ __forceinline__ void cp16(uint32_t smem_addr, const void* gptr) {
    asm volatile("cp.async.cg.shared.global [%0], [%1], 16;"
                 :: "r"(smem_addr), "l"(gptr));
}

// Block = (b, o-pair). Fully independent: computes s[b,o0], s[b,o1] from x[b],
// then stores its two 1MB output planes. No inter-block communication at all.
__global__ __launch_bounds__(256, 4) void fusedI(const float* __restrict__ x,
                                                 const float* __restrict__ wc,
                                                 const float* __restrict__ bc,
                                                 const float* __restrict__ wr,
                                                 const float* __restrict__ br,
                                                 float4* __restrict__ out) {
    __shared__ float2 xs2[2][CROWS * 256];   // 2 x 16 KB (8 rows x 512 floats)
    __shared__ float  Ucol[2][KK];           // col-dots per o             8 KB
    __shared__ float2 wrp[KK];               // (wr[o0,k], wr[o1,k])       4 KB
    __shared__ float2 wc_s[2 * 256];         // wc pairs per o             4 KB
    __shared__ float  red[2][8];
    __shared__ float  s_sh[2];

    const int b  = blockIdx.x >> 4;
    const int o0 = (blockIdx.x & 15) * 2;
    const int o1 = o0 + 1;
    const int t  = threadIdx.x;
    const int w  = t >> 5;      // warp id = row within chunk for U-part
    const int l  = t & 31;

    const float4* x4 = (const float4*)x;
    const size_t  xb = (size_t)b * (KK * KK / 4);
    const uint32_t sa[2] = {
        (uint32_t)__cvta_generic_to_shared(&xs2[0][0]),
        (uint32_t)__cvta_generic_to_shared(&xs2[1][0])
    };

    // prefetch chunk 0 (8 rows = 1024 float4)
#pragma unroll
    for (int i = 0; i < 4; i++)
        cp16(sa[0] + (uint32_t)(t + i * 256) * 16u, x4 + xb + t + i * 256);
    asm volatile("cp.async.commit_group;");

    // stage weights
    const float2* wc2 = (const float2*)wc;
#pragma unroll
    for (int i = 0; i < 2; i++) {
        int k = t + i * 256;
        wrp[k] = make_float2(wr[o0 * KK + k], wr[o1 * KK + k]);
    }
    wc_s[t]       = wc2[o0 * 256 + t];
    wc_s[256 + t] = wc2[o1 * 256 + t];

    unsigned long long V0 = 0ull, V1 = 0ull;   // row-dots for j = 2t, 2t+1

    for (int c = 0; c < NCHK; c++) {
        asm volatile("cp.async.wait_group 0;" ::: "memory");
        __syncthreads();

        if (c + 1 < NCHK) {
            const float4* src = x4 + xb + (size_t)(c + 1) * 1024;
            const uint32_t dst = sa[(c + 1) & 1];
#pragma unroll
            for (int i = 0; i < 4; i++)
                cp16(dst + (uint32_t)(t + i * 256) * 16u, src + t + i * 256);
            asm volatile("cp.async.commit_group;");
        }

        const float2* xsb = xs2[c & 1];

        // ---- U part: warp w owns staged row w; lanes cover k ----
        unsigned long long u0 = 0ull, u1 = 0ull;
#pragma unroll
        for (int m = 0; m < 8; m++) {
            F2U xv; xv.f = xsb[w * 256 + l + 32 * m];
            F2U c0; c0.f = wc_s[l + 32 * m];
            F2U c1; c1.f = wc_s[256 + l + 32 * m];
            u0 = ffma2(c0.u, xv.u, u0);
            u1 = ffma2(c1.u, xv.u, u1);
        }
        {
            F2U a; a.u = u0; F2U bq; bq.u = u1;
            float f0 = a.f.x + a.f.y;
            float f1 = bq.f.x + bq.f.y;
#pragma unroll
            for (int m = 16; m > 0; m >>= 1) {
                f0 += __shfl_xor_sync(0xffffffffu, f0, m);
                f1 += __shfl_xor_sync(0xffffffffu, f1, m);
            }
            if (l == 0) {
                Ucol[0][c * CROWS + w] = f0;
                Ucol[1][c * CROWS + w] = f1;
            }
        }

        // ---- V part: every thread, all 8 rows, its j-pair ----
#pragma unroll
        for (int r = 0; r < CROWS; r++) {
            float2 wv = wrp[c * CROWS + r];
            F2U xv; xv.f = xsb[r * 256 + t];
            V0 = ffma2(pack2(wv.x), xv.u, V0);
            V1 = ffma2(pack2(wv.y), xv.u, V1);
        }
    }
    __syncthreads();   // Ucol complete

    // ---- s = sum_k (row_k + br)(col_k + bc) ----
    {
        const float bc0 = bc[o0], bc1 = bc[o1];
        const float br0 = br[o0], br1 = br[o1];
        float2 uc0 = ((const float2*)Ucol[0])[t];
        float2 uc1 = ((const float2*)Ucol[1])[t];
        F2U v0; v0.u = V0; F2U v1; v1.u = V1;
        float a0 = (v0.f.x + br0) * (uc0.x + bc0) + (v0.f.y + br0) * (uc0.y + bc0);
        float a1 = (v1.f.x + br1) * (uc1.x + bc1) + (v1.f.y + br1) * (uc1.y + bc1);
#pragma unroll
        for (int m = 16; m > 0; m >>= 1) {
            a0 += __shfl_xor_sync(0xffffffffu, a0, m);
            a1 += __shfl_xor_sync(0xffffffffu, a1, m);
        }
        if (l == 0) { red[0][w] = a0; red[1][w] = a1; }
        __syncthreads();
        if (t < 2) {
            float s = 0.f;
#pragma unroll
            for (int i = 0; i < 8; i++) s += red[t][i];
            s_sh[t] = s;
        }
        __syncthreads();
    }

    // ---- store the two 1MB planes ----
    {
        const float s0 = s_sh[0];
        const float4 val0 = make_float4(s0, s0, s0, s0);
        float4* p0 = out + (size_t)(b * CC + o0) * 65536 + t;
#pragma unroll 16
        for (int i = 0; i < 256; i++) p0[i * 256] = val0;

        const float s1 = s_sh[1];
        const float4 val1 = make_float4(s1, s1, s1, s1);
        float4* p1 = out + (size_t)(b * CC + o1) * 65536 + t;
#pragma unroll 16
        for (int i = 0; i < 256; i++) p1[i * 256] = val1;
    }
}

extern "C" void kernel_launch(void* const* d_in, const int* in_sizes, int n_in,
                              void* d_out, int out_size) {
    const float* x  = (const float*)d_in[0];
    const float* wc = (const float*)d_in[1];
    const float* bc = (const float*)d_in[2];
    const float* wr = (const float*)d_in[3];
    const float* br = (const float*)d_in[4];

    fusedI<<<BB * 16, 256>>>(x, wc, bc, wr, br, (float4*)d_out);
}

// round 16
// speedup vs baseline: 1.8564x; 1.2282x over previous
#include <cuda_runtime.h>
#include <cuda_bf16.h>
#include <stdint.h>

#define BB 32
#define KK 512
#define CC 32
#define TILE 32
#define NT 16          // row tiles per batch (512/32)
#define NCH 2          // chunks of 16 rows per tile
#define GRP 8          // batches per group
#define NGRP 4

// Scratch (no allocations allowed)
__device__ float g_U[BB * KK * CC];        // U[b][k][o]                       (2 MB)
__device__ float g_Vp[BB * NT * CC * KK];  // per-tile partial V[b][t][o][j]   (32 MB)
__device__ float g_s[BB * CC];             // s[b][o]

union F2U { float2 f; unsigned long long u; };
union F4U { float4 f; unsigned long long u[2]; };

__device__ __forceinline__ unsigned long long ffma2(unsigned long long a,
                                                    unsigned long long b,
                                                    unsigned long long c) {
    unsigned long long d;
    asm("fma.rn.f32x2 %0, %1, %2, %3;" : "=l"(d) : "l"(a), "l"(b), "l"(c));
    return d;
}
__device__ __forceinline__ unsigned long long pack2(float v) {
    unsigned long long r;
    asm("mov.b64 %0, {%1, %1};" : "=l"(r) : "f"(v));
    return r;
}
__device__ __forceinline__ void cp16(uint32_t smem_addr, const void* gptr) {
    asm volatile("cp.async.cg.shared.global [%0], [%1], 16;"
                 :: "r"(smem_addr), "l"(gptr));
}

// ---------------------------------------------------------------------------
// Kernel A (per group): block = (b, 32-row tile), 512 threads, 128 blocks.
// o = t&31 (lane), w = t>>5 (warp = j-slice: 32 cols as 8 float4 at w+16q).
// cp.async double-buffered x staging; double-buffered cross-warp U reduce.
// ---------------------------------------------------------------------------
__global__ __launch_bounds__(512) void kA(const float* __restrict__ x,
                                          const float* __restrict__ wc,
                                          const float* __restrict__ wr,
                                          int b0) {
    const int b    = b0 + (blockIdx.x >> 4);
    const int tile = blockIdx.x & 15;
    const int i0   = tile * TILE;
    const int t    = threadIdx.x;
    const int o    = t & 31;
    const int w    = t >> 5;

    __shared__ float4 xs4[2][16 * (KK / 4)];        // 2 x 32 KB
    __shared__ float  wr_s[TILE * CC];              // 4 KB
    __shared__ float  u_part[2][16 * 16 * CC];      // 2 x 32 KB

    const float4* x4 = (const float4*)x;
    const size_t  xbase = (size_t)(b * KK + i0) * (KK / 4);
    const uint32_t xs_sa[2] = {
        (uint32_t)__cvta_generic_to_shared(&xs4[0][0]),
        (uint32_t)__cvta_generic_to_shared(&xs4[1][0])
    };

    // prefetch chunk 0 (16 rows = 2048 float4)
    {
        const float4* src = x4 + xbase;
#pragma unroll
        for (int i = 0; i < 4; i++)
            cp16(xs_sa[0] + (uint32_t)(t + i * 512) * 16u, src + t + i * 512);
        asm volatile("cp.async.commit_group;");
    }

    // preload w_row slice for this row-tile (rows i0..i0+31)
#pragma unroll
    for (int i = 0; i < (TILE * CC) / 512; i++) {
        int idx = t + i * 512;
        int rr = idx >> 5, oo = idx & 31;
        wr_s[idx] = wr[oo * KK + i0 + rr];
    }

    // w_col slice for this thread's (o, j-slice): 8 float4 = 16 packed f32x2
    unsigned long long wcr[16];
#pragma unroll
    for (int q = 0; q < 8; q++) {
        F4U v; v.f = ((const float4*)wc)[o * (KK / 4) + w + 16 * q];
        wcr[2 * q]     = v.u[0];
        wcr[2 * q + 1] = v.u[1];
    }

    unsigned long long Vacc[16];
#pragma unroll
    for (int q = 0; q < 16; q++) Vacc[q] = 0ull;

    for (int c = 0; c < NCH; c++) {
        asm volatile("cp.async.wait_group 0;" ::: "memory");
        __syncthreads();

        if (c + 1 < NCH) {
            const float4* src = x4 + xbase + (size_t)(c + 1) * 16 * (KK / 4);
            const uint32_t dst = xs_sa[(c + 1) & 1];
#pragma unroll
            for (int i = 0; i < 4; i++)
                cp16(dst + (uint32_t)(t + i * 512) * 16u, src + t + i * 512);
            asm volatile("cp.async.commit_group;");
        }

        if (c > 0) {
            const int pc = c - 1;
            const int rr = t >> 5, oo = t & 31;
            float s = 0.f;
#pragma unroll
            for (int wi = 0; wi < 16; wi++)
                s += u_part[pc & 1][(rr * 16 + wi) * 32 + oo];
            g_U[(size_t)(b * KK + i0 + pc * 16 + rr) * CC + oo] = s;
        }

        const float4* xsb = xs4[c & 1];
        float* upb = u_part[c & 1];
#pragma unroll
        for (int r = 0; r < 16; r++) {
            const int row = c * 16 + r;
            const unsigned long long wr2 = pack2(wr_s[row * 32 + o]);
            const float4* xr4 = xsb + r * (KK / 4);
            unsigned long long ua = 0ull, ub = 0ull;
#pragma unroll
            for (int q = 0; q < 8; q++) {
                F4U xv; xv.f = xr4[w + 16 * q];            // 32-lane broadcast
                Vacc[2 * q]     = ffma2(wr2, xv.u[0], Vacc[2 * q]);
                Vacc[2 * q + 1] = ffma2(wr2, xv.u[1], Vacc[2 * q + 1]);
                ua = ffma2(wcr[2 * q],     xv.u[0], ua);
                ub = ffma2(wcr[2 * q + 1], xv.u[1], ub);
            }
            F2U us; us.u = ua; F2U ut; ut.u = ub;
            upb[(r * 16 + w) * 32 + o] = (us.f.x + us.f.y) + (ut.f.x + ut.f.y);
        }
    }

    __syncthreads();
    // reduce last chunk's U partials
    {
        const int pc = NCH - 1;
        const int rr = t >> 5, oo = t & 31;
        float s = 0.f;
#pragma unroll
        for (int wi = 0; wi < 16; wi++)
            s += u_part[pc & 1][(rr * 16 + wi) * 32 + oo];
        g_U[(size_t)(b * KK + i0 + pc * 16 + rr) * CC + oo] = s;
    }

    // per-tile V partial writeback: g_Vp[((b*NT+tile)*CC+o)*KK + j]
    float4* Vg4 = (float4*)(g_Vp + (size_t)(((b * NT + tile) * CC) + o) * KK);
#pragma unroll
    for (int q = 0; q < 8; q++) {
        F4U v; v.u[0] = Vacc[2 * q]; v.u[1] = Vacc[2 * q + 1];
        Vg4[w + 16 * q] = v.f;
    }
}

// ---------------------------------------------------------------------------
// Kernel A2 (per group): s[b,o] = sum_k (sum_tiles Vp + b_row)(U + b_col)
// grid = GRP*32 blocks of 128 threads
// ---------------------------------------------------------------------------
__global__ __launch_bounds__(128) void kA2(const float* __restrict__ bc,
                                           const float* __restrict__ br,
                                           int b0) {
    const int b = b0 + (blockIdx.x >> 5);
    const int o = blockIdx.x & 31;
    const int t = threadIdx.x;
    const float bcv = bc[o], brv = br[o];

    float acc = 0.f;
    for (int k = t; k < KK; k += 128) {
        float u = g_U[(size_t)(b * KK + k) * CC + o] + bcv;
        float v = brv;
#pragma unroll
        for (int tile = 0; tile < NT; tile++)
            v += g_Vp[(size_t)(((b * NT + tile) * CC) + o) * KK + k];
        acc += u * v;
    }
    acc += __shfl_xor_sync(0xffffffffu, acc, 16);
    acc += __shfl_xor_sync(0xffffffffu, acc, 8);
    acc += __shfl_xor_sync(0xffffffffu, acc, 4);
    acc += __shfl_xor_sync(0xffffffffu, acc, 2);
    acc += __shfl_xor_sync(0xffffffffu, acc, 1);

    __shared__ float red[4];
    if ((t & 31) == 0) red[t >> 5] = acc;
    __syncthreads();
    if (t == 0) g_s[b * CC + o] = red[0] + red[1] + red[2] + red[3];
}

// ---------------------------------------------------------------------------
// Kernel B (per group): broadcast fill of 256 planes (64KB per block).
// ---------------------------------------------------------------------------
__global__ __launch_bounds__(256) void kB(float4* __restrict__ out, int p0) {
    const int P = p0 + (blockIdx.x >> 4);
    const int chunk = blockIdx.x & 15;
    const float v = g_s[P];
    const float4 val = make_float4(v, v, v, v);
    float4* p = out + (size_t)P * 65536 + (size_t)chunk * 4096 + threadIdx.x;
#pragma unroll
    for (int q = 0; q < 16; q++) p[q * 256] = val;
}

extern "C" void kernel_launch(void* const* d_in, const int* in_sizes, int n_in,
                              void* d_out, int out_size) {
    const float* x  = (const float*)d_in[0];
    const float* wc = (const float*)d_in[1];
    const float* bc = (const float*)d_in[2];
    const float* wr = (const float*)d_in[3];
    const float* br = (const float*)d_in[4];

    // Lazy one-time resource setup. First call is the (non-captured)
    // correctness run, so no creation happens during graph capture.
    static cudaStream_t cs = nullptr;   // compute stream (high priority)
    static cudaStream_t ss = nullptr;   // store stream  (low priority)
    static cudaEvent_t  eS, eA[NGRP], eF;
    if (cs == nullptr) {
        int lo, hi;
        cudaDeviceGetStreamPriorityRange(&lo, &hi);
        cudaStreamCreateWithPriority(&cs, cudaStreamNonBlocking, hi);
        cudaStreamCreateWithPriority(&ss, cudaStreamNonBlocking, lo);
        cudaEventCreateWithFlags(&eS, cudaEventDisableTiming);
        for (int q = 0; q < NGRP; q++)
            cudaEventCreateWithFlags(&eA[q], cudaEventDisableTiming);
        cudaEventCreateWithFlags(&eF, cudaEventDisableTiming);
    }

    // fork from the (possibly capturing) default stream
    cudaEventRecord(eS, 0);
    cudaStreamWaitEvent(cs, eS, 0);
    cudaStreamWaitEvent(ss, eS, 0);

    // compute pipeline: group q's s values ready at eA[q]
    for (int q = 0; q < NGRP; q++) {
        kA <<<128, 512, 0, cs>>>(x, wc, wr, q * GRP);
        kA2<<<GRP * 32, 128, 0, cs>>>(bc, br, q * GRP);
        cudaEventRecord(eA[q], cs);
    }

    // store pipeline: each group's stores gated only on its own compute
    for (int q = 0; q < NGRP; q++) {
        cudaStreamWaitEvent(ss, eA[q], 0);
        kB<<<GRP * 32 * 16, 256, 0, ss>>>((float4*)d_out, q * GRP * CC);
    }

    // join back to the default stream
    cudaEventRecord(eF, ss);
    cudaStreamWaitEvent(0, eF, 0);
}